// round 4
// baseline (speedup 1.0000x reference)
#include <cuda_runtime.h>

// ---------------------------------------------------------------------------
// SwinIR-lite forward: conv3x3(3->60) -> 36 x [LN+WindowAttn+res, LN+MLP+res]
// -> conv3x3(60->12) + PixelShuffle(2).  All fp32.  B=2, H=W=128, C=60.
// R3: occupancy repair (launch_bounds caps, 8-wide M blocking) + packed
//     fma.rn.f32x2 in all inner loops.
// ---------------------------------------------------------------------------

constexpr int Bn   = 2;
constexpr int Hc   = 128;
constexpr int Wc   = 128;
constexpr int Cch  = 60;
constexpr int NHEADS = 3;
constexpr int NTOK = Bn * Hc * Wc;          // 32768 tokens
constexpr int QKVC = 180;
constexpr int FCC  = 120;
constexpr int NL   = 36;

// Scratch (device globals; no allocation allowed)
__device__ float g_feat[NTOK * Cch];        // 7.5 MB
__device__ float g_qkv [NTOK * QKVC];       // 22.5 MB
__device__ float g_attn[NTOK * Cch];        // 7.5 MB
__device__ float g_mlp [NTOK * FCC];        // 15 MB

// ---- packed f32x2 helpers (Blackwell sm_100+) ------------------------------
__device__ __forceinline__ float2 pack2(float v) {
    float2 r;
    asm("mov.b64 %0, {%1, %1};"
        : "=l"(reinterpret_cast<unsigned long long&>(r)) : "f"(v));
    return r;
}
// d = a*b + d  (2 lanes)
__device__ __forceinline__ void ffma2(float2& d, float2 a, float2 b) {
    asm("fma.rn.f32x2 %0, %1, %2, %0;"
        : "+l"(reinterpret_cast<unsigned long long&>(d))
        : "l"(reinterpret_cast<unsigned long long&>(a)),
          "l"(reinterpret_cast<unsigned long long&>(b)));
}

// ---------------------------------------------------------------------------
// conv3x3 3->60, NCHW in -> NHWC (token-major) out
// ---------------------------------------------------------------------------
__global__ __launch_bounds__(256) void conv_in_k(
    const float* __restrict__ x, const float* __restrict__ w,
    const float* __restrict__ b)
{
    int idx = blockIdx.x * blockDim.x + threadIdx.x;
    if (idx >= NTOK * Cch) return;
    int co = idx % Cch;
    int p  = idx / Cch;
    int wx = p % Wc;
    int hy = (p / Wc) % Hc;
    int bb = p / (Wc * Hc);
    float acc = b[co];
#pragma unroll
    for (int ci = 0; ci < 3; ci++) {
#pragma unroll
        for (int kh = 0; kh < 3; kh++) {
            int hh = hy + kh - 1;
            if ((unsigned)hh >= (unsigned)Hc) continue;
#pragma unroll
            for (int kw = 0; kw < 3; kw++) {
                int ww2 = wx + kw - 1;
                if ((unsigned)ww2 >= (unsigned)Wc) continue;
                acc += x[((bb * 3 + ci) * Hc + hh) * Wc + ww2] *
                       w[((co * 3 + ci) * 3 + kh) * 3 + kw];
            }
        }
    }
    g_feat[idx] = acc;
}

// ---------------------------------------------------------------------------
// LN (over K=60) + GEMM [T,K]@[K,N] + bias (+ optional Swish).
// Block: NP*MG threads; tile TM tokens; 8 accumulators/thread via f32x2.
// ---------------------------------------------------------------------------
template <int K, int N, int NP, int MG, int TM, bool SWISH, bool OUT_MLP, int MINB>
__global__ __launch_bounds__(NP * MG, MINB) void ln_gemm_k(
    const float* __restrict__ gamma, const float* __restrict__ beta,
    const float* __restrict__ w, const float* __restrict__ bias)
{
    extern __shared__ float sm[];
    float* ws = sm;                  // K*N
    float* bs = sm + K * N;          // N
    float* gs = bs + N;              // K (gamma)
    float* bt = gs + K;              // K (beta)
    float* xs = bt + K;              // K*TM (k-major)
    const int tid = threadIdx.x;
    const int T0  = blockIdx.x * TM;

    for (int i = tid; i < K * N; i += NP * MG) ws[i] = w[i];
    for (int i = tid; i < N; i += NP * MG)     bs[i] = bias[i];
    for (int i = tid; i < K; i += NP * MG)   { gs[i] = gamma[i]; bt[i] = beta[i]; }
    __syncthreads();

    if (tid < TM) {
        const float4* row = (const float4*)(g_feat + (size_t)(T0 + tid) * K);
        float s = 0.f, s2 = 0.f;
#pragma unroll
        for (int i = 0; i < K / 4; i++) {
            float4 v = row[i];
            s  += v.x + v.y + v.z + v.w;
            s2 += v.x * v.x + v.y * v.y + v.z * v.z + v.w * v.w;
            xs[(4 * i + 0) * TM + tid] = v.x;
            xs[(4 * i + 1) * TM + tid] = v.y;
            xs[(4 * i + 2) * TM + tid] = v.z;
            xs[(4 * i + 3) * TM + tid] = v.w;
        }
        float mu  = s * (1.0f / K);
        float var = s2 * (1.0f / K) - mu * mu;
        float rs  = rsqrtf(var + 1e-5f);
#pragma unroll
        for (int k = 0; k < K; k++)
            xs[k * TM + tid] = (xs[k * TM + tid] - mu) * rs * gs[k] + bt[k];
    }
    __syncthreads();

    const int n   = tid % NP;
    const int grp = tid / NP;
    if (n < N) {
        float* out = OUT_MLP ? g_mlp : g_qkv;
        const float bv = bs[n];
        const int mper = TM / MG;
#pragma unroll 1
        for (int m0 = grp * mper; m0 < (grp + 1) * mper; m0 += 8) {
            float2 a0 = make_float2(bv, bv), a1 = a0, a2 = a0, a3 = a0;
#pragma unroll
            for (int k = 0; k < K; k++) {
                float2 wp = pack2(ws[k * N + n]);
                float4 x0 = *(const float4*)(xs + k * TM + m0);
                float4 x1 = *(const float4*)(xs + k * TM + m0 + 4);
                ffma2(a0, make_float2(x0.x, x0.y), wp);
                ffma2(a1, make_float2(x0.z, x0.w), wp);
                ffma2(a2, make_float2(x1.x, x1.y), wp);
                ffma2(a3, make_float2(x1.z, x1.w), wp);
            }
            if (SWISH) {
                a0.x /= 1.f + __expf(-a0.x);  a0.y /= 1.f + __expf(-a0.y);
                a1.x /= 1.f + __expf(-a1.x);  a1.y /= 1.f + __expf(-a1.y);
                a2.x /= 1.f + __expf(-a2.x);  a2.y /= 1.f + __expf(-a2.y);
                a3.x /= 1.f + __expf(-a3.x);  a3.y /= 1.f + __expf(-a3.y);
            }
            size_t o = (size_t)(T0 + m0) * N + n;
            out[o]         = a0.x;  out[o +     N] = a0.y;
            out[o + 2 * N] = a1.x;  out[o + 3 * N] = a1.y;
            out[o + 4 * N] = a2.x;  out[o + 5 * N] = a2.y;
            out[o + 6 * N] = a3.x;  out[o + 7 * N] = a3.y;
        }
    }
}

// ---------------------------------------------------------------------------
// GEMM [T,K]@[K,N] + bias + residual-add into g_feat.
// ---------------------------------------------------------------------------
template <int K, int N, int NP, int MG, int TM, bool IN_MLP, int MINB>
__global__ __launch_bounds__(NP * MG, MINB) void gemm_resid_k(
    const float* __restrict__ w, const float* __restrict__ bias)
{
    extern __shared__ float sm[];
    float* ws = sm;
    float* bs = sm + K * N;
    float* xs = bs + N;
    const int tid = threadIdx.x;
    const int T0  = blockIdx.x * TM;
    const float* in = IN_MLP ? g_mlp : g_attn;

    for (int i = tid; i < K * N; i += NP * MG) ws[i] = w[i];
    for (int i = tid; i < N; i += NP * MG)     bs[i] = bias[i];

    if (tid < TM) {
        const float4* row = (const float4*)(in + (size_t)(T0 + tid) * K);
#pragma unroll
        for (int i = 0; i < K / 4; i++) {
            float4 v = row[i];
            xs[(4 * i + 0) * TM + tid] = v.x;
            xs[(4 * i + 1) * TM + tid] = v.y;
            xs[(4 * i + 2) * TM + tid] = v.z;
            xs[(4 * i + 3) * TM + tid] = v.w;
        }
    }
    __syncthreads();

    const int n   = tid % NP;
    const int grp = tid / NP;
    if (n < N) {
        const float bv = bs[n];
        const int mper = TM / MG;
#pragma unroll 1
        for (int m0 = grp * mper; m0 < (grp + 1) * mper; m0 += 8) {
            float2 a0 = make_float2(bv, bv), a1 = a0, a2 = a0, a3 = a0;
#pragma unroll
            for (int k = 0; k < K; k++) {
                float2 wp = pack2(ws[k * N + n]);
                float4 x0 = *(const float4*)(xs + k * TM + m0);
                float4 x1 = *(const float4*)(xs + k * TM + m0 + 4);
                ffma2(a0, make_float2(x0.x, x0.y), wp);
                ffma2(a1, make_float2(x0.z, x0.w), wp);
                ffma2(a2, make_float2(x1.x, x1.y), wp);
                ffma2(a3, make_float2(x1.z, x1.w), wp);
            }
            size_t o = (size_t)(T0 + m0) * N + n;
            g_feat[o]         += a0.x;  g_feat[o +     N] += a0.y;
            g_feat[o + 2 * N] += a1.x;  g_feat[o + 3 * N] += a1.y;
            g_feat[o + 4 * N] += a2.x;  g_feat[o + 5 * N] += a2.y;
            g_feat[o + 6 * N] += a3.x;  g_feat[o + 7 * N] += a3.y;
        }
    }
}

// ---------------------------------------------------------------------------
// Window attention.  Block = (window, head), 256 threads = 256 queries.
// Roll by index arithmetic; streaming softmax w/o max-subtract; f32x2 math.
// ---------------------------------------------------------------------------
__global__ __launch_bounds__(256, 3) void attn_k(int wh, int ww, int sh, int sw,
                                                 int shifted)
{
    __shared__ float4 ks [256][5];
    __shared__ float4 vsm[256][5];
    __shared__ int    rg [256];

    const int n    = threadIdx.x;
    const int head = blockIdx.y;
    const int win  = blockIdx.x;
    const int nW   = Wc / ww;
    const int perB = (Hc / wh) * nW;
    const int b    = win / perB;
    const int wr_  = win % perB;
    const int wy   = wr_ / nW, wx = wr_ % nW;
    const int iy   = n / ww,   ix = n % ww;
    const int hr   = wy * wh + iy;
    const int wrr  = wx * ww + ix;
    int hs = hr + sh;   if (hs  >= Hc) hs  -= Hc;
    int wsv = wrr + sw; if (wsv >= Wc) wsv -= Wc;
    const size_t g = ((size_t)b * Hc + hs) * Wc + wsv;

    const float4* qp    = (const float4*)g_qkv;
    const size_t  base4 = g * 45 + (size_t)head * 5;   // 180 floats / token
    const float   scale = 0.223606797749979f;          // 20^-0.5

    float2 q2[10];
#pragma unroll
    for (int i = 0; i < 5; i++) {
        float4 t = qp[base4 + i];
        q2[2 * i]     = make_float2(t.x * scale, t.y * scale);
        q2[2 * i + 1] = make_float2(t.z * scale, t.w * scale);
        ks [n][i] = qp[base4 + 15 + i];
        vsm[n][i] = qp[base4 + 30 + i];
    }
    int myreg = 0;
    if (shifted) {
        int rh = (hr  < Hc - wh) ? 0 : ((hr  < Hc - sh) ? 1 : 2);
        int rw = (wrr < Wc - ww) ? 0 : ((wrr < Wc - sw) ? 1 : 2);
        myreg = rh * 3 + rw;
        rg[n] = myreg;
    }
    __syncthreads();

    float2 acc2[10];
#pragma unroll
    for (int i = 0; i < 10; i++) acc2[i] = make_float2(0.f, 0.f);
    float denom = 0.f;

    if (shifted) {
        for (int m = 0; m < 256; m++) {
            float2 d0 = make_float2(0.f, 0.f), d1 = d0;
#pragma unroll
            for (int i = 0; i < 5; i++) {
                float4 kv = ks[m][i];
                ffma2(d0, q2[2 * i],     make_float2(kv.x, kv.y));
                ffma2(d1, q2[2 * i + 1], make_float2(kv.z, kv.w));
            }
            float s = d0.x + d0.y + d1.x + d1.y;
            if (rg[m] != myreg) s -= 100.f;
            float p = __expf(s);
            denom += p;
            float2 pp = pack2(p);
#pragma unroll
            for (int i = 0; i < 5; i++) {
                float4 vv = vsm[m][i];
                ffma2(acc2[2 * i],     make_float2(vv.x, vv.y), pp);
                ffma2(acc2[2 * i + 1], make_float2(vv.z, vv.w), pp);
            }
        }
    } else {
        for (int m = 0; m < 256; m++) {
            float2 d0 = make_float2(0.f, 0.f), d1 = d0;
#pragma unroll
            for (int i = 0; i < 5; i++) {
                float4 kv = ks[m][i];
                ffma2(d0, q2[2 * i],     make_float2(kv.x, kv.y));
                ffma2(d1, q2[2 * i + 1], make_float2(kv.z, kv.w));
            }
            float s = d0.x + d0.y + d1.x + d1.y;
            float p = __expf(s);
            denom += p;
            float2 pp = pack2(p);
#pragma unroll
            for (int i = 0; i < 5; i++) {
                float4 vv = vsm[m][i];
                ffma2(acc2[2 * i],     make_float2(vv.x, vv.y), pp);
                ffma2(acc2[2 * i + 1], make_float2(vv.z, vv.w), pp);
            }
        }
    }

    float inv = 1.f / denom;
    float4* op = (float4*)g_attn;
    size_t  ob = g * 15 + (size_t)head * 5;     // 60 floats / token
#pragma unroll
    for (int i = 0; i < 5; i++) {
        op[ob + i] = make_float4(acc2[2 * i].x * inv,  acc2[2 * i].y * inv,
                                 acc2[2 * i + 1].x * inv, acc2[2 * i + 1].y * inv);
    }
}

// ---------------------------------------------------------------------------
// conv3x3 60->12 + PixelShuffle(2) fused.
// ---------------------------------------------------------------------------
__global__ __launch_bounds__(256) void conv_out_k(
    const float* __restrict__ lw, const float* __restrict__ lb,
    float* __restrict__ out)
{
    const int TOT = Bn * 3 * 256 * 256;
    int idx = blockIdx.x * blockDim.x + threadIdx.x;
    if (idx >= TOT) return;
    int w2 = idx & 255;
    int h2 = (idx >> 8) & 255;
    int c  = (idx >> 16) % 3;
    int bb = idx / (3 * 65536);
    int co = c * 4 + (h2 & 1) * 2 + (w2 & 1);
    int h  = h2 >> 1, w = w2 >> 1;
    float acc = lb[co];
#pragma unroll
    for (int kh = 0; kh < 3; kh++) {
        int hh = h + kh - 1;
        if ((unsigned)hh >= (unsigned)Hc) continue;
#pragma unroll
        for (int kw = 0; kw < 3; kw++) {
            int ww2 = w + kw - 1;
            if ((unsigned)ww2 >= (unsigned)Wc) continue;
            const float* fp = g_feat + ((size_t)(bb * Hc + hh) * Wc + ww2) * Cch;
            const float* wp = lw + co * (Cch * 9) + kh * 3 + kw;
#pragma unroll
            for (int ci = 0; ci < Cch; ci++)
                acc = fmaf(fp[ci], wp[ci * 9], acc);
        }
    }
    out[idx] = acc;
}

// ---------------------------------------------------------------------------
// Launch
// ---------------------------------------------------------------------------
extern "C" void kernel_launch(void* const* d_in, const int* in_sizes, int n_in,
                              void* d_out, int out_size)
{
    (void)in_sizes; (void)n_in; (void)out_size;
    const float* x      = (const float*)d_in[0];
    const float* conv_w = (const float*)d_in[1];
    const float* conv_b = (const float*)d_in[2];
    const float* ln1_g  = (const float*)d_in[3];
    const float* ln1_b  = (const float*)d_in[4];
    const float* qkv_w  = (const float*)d_in[5];
    const float* qkv_b  = (const float*)d_in[6];
    const float* proj_w = (const float*)d_in[7];
    const float* proj_b = (const float*)d_in[8];
    const float* ln2_g  = (const float*)d_in[9];
    const float* ln2_b  = (const float*)d_in[10];
    const float* fc1_w  = (const float*)d_in[11];
    const float* fc1_b  = (const float*)d_in[12];
    const float* fc2_w  = (const float*)d_in[13];
    const float* fc2_b  = (const float*)d_in[14];
    const float* last_w = (const float*)d_in[15];
    const float* last_b = (const float*)d_in[16];
    float* out = (float*)d_out;

    // smem sizes (bytes)
    constexpr int SM_QKV  = (60 * 180 + 180 + 120 + 60 * 64)  * 4;  // 59760
    constexpr int SM_FC1  = (60 * 120 + 120 + 120 + 60 * 64)  * 4;  // 45120
    constexpr int SM_PROJ = (60 * 60  + 60  + 60 * 128) * 4;        // 45360
    constexpr int SM_FC2  = (120 * 60 + 60  + 120 * 64) * 4;        // 59760

    cudaFuncSetAttribute(ln_gemm_k<60, 180, 180, 2, 64, false, false, 3>,
                         cudaFuncAttributeMaxDynamicSharedMemorySize, SM_QKV);
    cudaFuncSetAttribute(ln_gemm_k<60, 120, 128, 2, 64, true, true, 4>,
                         cudaFuncAttributeMaxDynamicSharedMemorySize, SM_FC1);
    cudaFuncSetAttribute(gemm_resid_k<60, 60, 64, 4, 128, false, 4>,
                         cudaFuncAttributeMaxDynamicSharedMemorySize, SM_PROJ);
    cudaFuncSetAttribute(gemm_resid_k<120, 60, 64, 4, 64, true, 3>,
                         cudaFuncAttributeMaxDynamicSharedMemorySize, SM_FC2);

    conv_in_k<<<(NTOK * Cch + 255) / 256, 256>>>(x, conv_w, conv_b);

    for (int l = 0; l < NL; l++) {
        int i  = l % 6;
        int wi = i % 2;
        int wh = wi ? 8 : 32;
        int ww = wi ? 32 : 8;
        int shifted = (i % 4) >= 2;
        int sh = shifted ? (wi ? 4 : 16) : 0;
        int sw = shifted ? (wi ? 16 : 4) : 0;

        ln_gemm_k<60, 180, 180, 2, 64, false, false, 3>
            <<<NTOK / 64, 360, SM_QKV>>>(ln1_g + l * 60, ln1_b + l * 60,
                                         qkv_w + (size_t)l * 60 * 180,
                                         qkv_b + l * 180);

        attn_k<<<dim3(Bn * 64, NHEADS), 256>>>(wh, ww, sh, sw, shifted);

        gemm_resid_k<60, 60, 64, 4, 128, false, 4>
            <<<NTOK / 128, 256, SM_PROJ>>>(proj_w + (size_t)l * 3600,
                                           proj_b + l * 60);

        ln_gemm_k<60, 120, 128, 2, 64, true, true, 4>
            <<<NTOK / 64, 256, SM_FC1>>>(ln2_g + l * 60, ln2_b + l * 60,
                                         fc1_w + (size_t)l * 7200,
                                         fc1_b + l * 120);

        gemm_resid_k<120, 60, 64, 4, 64, true, 3>
            <<<NTOK / 64, 256, SM_FC2>>>(fc2_w + (size_t)l * 7200,
                                         fc2_b + l * 60);
    }

    conv_out_k<<<(Bn * 3 * 256 * 256 + 255) / 256, 256>>>(last_w, last_b, out);
}

// round 5
// speedup vs baseline: 1.0625x; 1.0625x over previous
#include <cuda_runtime.h>

// ---------------------------------------------------------------------------
// SwinIR-lite forward: conv3x3(3->60) -> 36 x [LN+WindowAttn+res, LN+MLP+res]
// -> conv3x3(60->12) + PixelShuffle(2).  All fp32.  B=2, H=W=128, C=60.
// R4: revert f32x2 (regressed); fix grid-limited occupancy (TM=32 -> grid 1024),
//     8 outputs/thread for issue-ratio + ILP, split attention into half-blocks.
// ---------------------------------------------------------------------------

constexpr int Bn   = 2;
constexpr int Hc   = 128;
constexpr int Wc   = 128;
constexpr int Cch  = 60;
constexpr int NHEADS = 3;
constexpr int NTOK = Bn * Hc * Wc;          // 32768 tokens
constexpr int QKVC = 180;
constexpr int FCC  = 120;
constexpr int NL   = 36;

// Scratch (device globals; no allocation allowed)
__device__ float g_feat[NTOK * Cch];        // 7.5 MB
__device__ float g_qkv [NTOK * QKVC];       // 22.5 MB
__device__ float g_attn[NTOK * Cch];        // 7.5 MB
__device__ float g_mlp [NTOK * FCC];        // 15 MB

// ---------------------------------------------------------------------------
// conv3x3 3->60, NCHW in -> NHWC (token-major) out
// ---------------------------------------------------------------------------
__global__ __launch_bounds__(256) void conv_in_k(
    const float* __restrict__ x, const float* __restrict__ w,
    const float* __restrict__ b)
{
    int idx = blockIdx.x * blockDim.x + threadIdx.x;
    if (idx >= NTOK * Cch) return;
    int co = idx % Cch;
    int p  = idx / Cch;
    int wx = p % Wc;
    int hy = (p / Wc) % Hc;
    int bb = p / (Wc * Hc);
    float acc = b[co];
#pragma unroll
    for (int ci = 0; ci < 3; ci++) {
#pragma unroll
        for (int kh = 0; kh < 3; kh++) {
            int hh = hy + kh - 1;
            if ((unsigned)hh >= (unsigned)Hc) continue;
#pragma unroll
            for (int kw = 0; kw < 3; kw++) {
                int ww2 = wx + kw - 1;
                if ((unsigned)ww2 >= (unsigned)Wc) continue;
                acc += x[((bb * 3 + ci) * Hc + hh) * Wc + ww2] *
                       w[((co * 3 + ci) * 3 + kh) * 3 + kw];
            }
        }
    }
    g_feat[idx] = acc;
}

// ---------------------------------------------------------------------------
// LN (over K=60) + GEMM [T,K]@[K,N] + bias (+ optional Swish).
// Block: NP*MG threads; tile TM tokens; 8 outputs/thread.
// ---------------------------------------------------------------------------
template <int K, int N, int NP, int MG, int TM, bool SWISH, bool OUT_MLP, int MINB>
__global__ __launch_bounds__(NP * MG, MINB) void ln_gemm_k(
    const float* __restrict__ gamma, const float* __restrict__ beta,
    const float* __restrict__ w, const float* __restrict__ bias)
{
    extern __shared__ float sm[];
    float* ws = sm;                  // K*N
    float* bs = sm + K * N;          // N
    float* gs = bs + N;              // K (gamma)
    float* bt = gs + K;              // K (beta)
    float* xs = bt + K;              // K*TM (k-major)
    const int tid = threadIdx.x;
    const int T0  = blockIdx.x * TM;

    for (int i = tid; i < K * N; i += NP * MG) ws[i] = w[i];
    for (int i = tid; i < N; i += NP * MG)     bs[i] = bias[i];
    for (int i = tid; i < K; i += NP * MG)   { gs[i] = gamma[i]; bt[i] = beta[i]; }
    __syncthreads();

    if (tid < TM) {
        const float4* row = (const float4*)(g_feat + (size_t)(T0 + tid) * K);
        float s = 0.f, s2 = 0.f;
#pragma unroll
        for (int i = 0; i < K / 4; i++) {
            float4 v = row[i];
            s  += v.x + v.y + v.z + v.w;
            s2 += v.x * v.x + v.y * v.y + v.z * v.z + v.w * v.w;
            xs[(4 * i + 0) * TM + tid] = v.x;
            xs[(4 * i + 1) * TM + tid] = v.y;
            xs[(4 * i + 2) * TM + tid] = v.z;
            xs[(4 * i + 3) * TM + tid] = v.w;
        }
        float mu  = s * (1.0f / K);
        float var = s2 * (1.0f / K) - mu * mu;
        float rs  = rsqrtf(var + 1e-5f);
#pragma unroll
        for (int k = 0; k < K; k++)
            xs[k * TM + tid] = (xs[k * TM + tid] - mu) * rs * gs[k] + bt[k];
    }
    __syncthreads();

    const int n   = tid % NP;
    const int grp = tid / NP;
    if (n < N) {
        float* out = OUT_MLP ? g_mlp : g_qkv;
        const float bv = bs[n];
        const int mper = TM / MG;
#pragma unroll
        for (int it = 0; it < mper / 8; it++) {
            const int m0 = grp * mper + it * 8;
            float a0 = bv, a1 = bv, a2 = bv, a3 = bv;
            float a4 = bv, a5 = bv, a6 = bv, a7 = bv;
#pragma unroll
            for (int k = 0; k < K; k++) {
                float  wv = ws[k * N + n];
                float4 x0 = *(const float4*)(xs + k * TM + m0);
                float4 x1 = *(const float4*)(xs + k * TM + m0 + 4);
                a0 = fmaf(x0.x, wv, a0);
                a1 = fmaf(x0.y, wv, a1);
                a2 = fmaf(x0.z, wv, a2);
                a3 = fmaf(x0.w, wv, a3);
                a4 = fmaf(x1.x, wv, a4);
                a5 = fmaf(x1.y, wv, a5);
                a6 = fmaf(x1.z, wv, a6);
                a7 = fmaf(x1.w, wv, a7);
            }
            if (SWISH) {
                a0 /= 1.f + __expf(-a0);  a1 /= 1.f + __expf(-a1);
                a2 /= 1.f + __expf(-a2);  a3 /= 1.f + __expf(-a3);
                a4 /= 1.f + __expf(-a4);  a5 /= 1.f + __expf(-a5);
                a6 /= 1.f + __expf(-a6);  a7 /= 1.f + __expf(-a7);
            }
            size_t o = (size_t)(T0 + m0) * N + n;
            out[o]         = a0;  out[o +     N] = a1;
            out[o + 2 * N] = a2;  out[o + 3 * N] = a3;
            out[o + 4 * N] = a4;  out[o + 5 * N] = a5;
            out[o + 6 * N] = a6;  out[o + 7 * N] = a7;
        }
    }
}

// ---------------------------------------------------------------------------
// GEMM [T,K]@[K,N] + bias + residual-add into g_feat.
// ---------------------------------------------------------------------------
template <int K, int N, int NP, int MG, int TM, bool IN_MLP, int MINB>
__global__ __launch_bounds__(NP * MG, MINB) void gemm_resid_k(
    const float* __restrict__ w, const float* __restrict__ bias)
{
    extern __shared__ float sm[];
    float* ws = sm;
    float* bs = sm + K * N;
    float* xs = bs + N;
    const int tid = threadIdx.x;
    const int T0  = blockIdx.x * TM;
    const float* in = IN_MLP ? g_mlp : g_attn;

    for (int i = tid; i < K * N; i += NP * MG) ws[i] = w[i];
    for (int i = tid; i < N; i += NP * MG)     bs[i] = bias[i];

    if (tid < TM) {
        const float4* row = (const float4*)(in + (size_t)(T0 + tid) * K);
#pragma unroll
        for (int i = 0; i < K / 4; i++) {
            float4 v = row[i];
            xs[(4 * i + 0) * TM + tid] = v.x;
            xs[(4 * i + 1) * TM + tid] = v.y;
            xs[(4 * i + 2) * TM + tid] = v.z;
            xs[(4 * i + 3) * TM + tid] = v.w;
        }
    }
    __syncthreads();

    const int n   = tid % NP;
    const int grp = tid / NP;
    if (n < N) {
        const float bv = bs[n];
        const int mper = TM / MG;
#pragma unroll
        for (int it = 0; it < mper / 8; it++) {
            const int m0 = grp * mper + it * 8;
            float a0 = bv, a1 = bv, a2 = bv, a3 = bv;
            float a4 = bv, a5 = bv, a6 = bv, a7 = bv;
#pragma unroll
            for (int k = 0; k < K; k++) {
                float  wv = ws[k * N + n];
                float4 x0 = *(const float4*)(xs + k * TM + m0);
                float4 x1 = *(const float4*)(xs + k * TM + m0 + 4);
                a0 = fmaf(x0.x, wv, a0);
                a1 = fmaf(x0.y, wv, a1);
                a2 = fmaf(x0.z, wv, a2);
                a3 = fmaf(x0.w, wv, a3);
                a4 = fmaf(x1.x, wv, a4);
                a5 = fmaf(x1.y, wv, a5);
                a6 = fmaf(x1.z, wv, a6);
                a7 = fmaf(x1.w, wv, a7);
            }
            size_t o = (size_t)(T0 + m0) * N + n;
            g_feat[o]         += a0;  g_feat[o +     N] += a1;
            g_feat[o + 2 * N] += a2;  g_feat[o + 3 * N] += a3;
            g_feat[o + 4 * N] += a4;  g_feat[o + 5 * N] += a5;
            g_feat[o + 6 * N] += a6;  g_feat[o + 7 * N] += a7;
        }
    }
}

// ---------------------------------------------------------------------------
// Window attention.  Block = (window, head, half); 128 threads = 128 queries,
// full 256-key window K/V in smem.  Roll by index arithmetic; streaming
// softmax without max-subtract (logits tiny; masked = -100).
// ---------------------------------------------------------------------------
__global__ __launch_bounds__(128, 5) void attn_k(int wh, int ww, int sh, int sw,
                                                 int shifted)
{
    __shared__ float4 ks [256][5];
    __shared__ float4 vsm[256][5];
    __shared__ int    rg [256];

    const int tid  = threadIdx.x;
    const int head = blockIdx.y >> 1;
    const int half = blockIdx.y & 1;
    const int win  = blockIdx.x;
    const int nW   = Wc / ww;
    const int perB = (Hc / wh) * nW;
    const int b    = win / perB;
    const int wr_  = win % perB;
    const int wy   = wr_ / nW, wx = wr_ % nW;

    const float4* qp = (const float4*)g_qkv;

    // load 2 K/V rows per thread (keys tid, tid+128)
#pragma unroll
    for (int r = 0; r < 2; r++) {
        int m   = tid + r * 128;
        int iy  = m / ww, ix = m % ww;
        int hr  = wy * wh + iy;
        int wrr = wx * ww + ix;
        int hs  = hr + sh;   if (hs  >= Hc) hs  -= Hc;
        int wsv = wrr + sw;  if (wsv >= Wc) wsv -= Wc;
        size_t gk = ((size_t)b * Hc + hs) * Wc + wsv;
        size_t b4 = gk * 45 + (size_t)head * 5;
#pragma unroll
        for (int i = 0; i < 5; i++) {
            ks [m][i] = qp[b4 + 15 + i];
            vsm[m][i] = qp[b4 + 30 + i];
        }
        if (shifted) {
            int rh = (hr  < Hc - wh) ? 0 : ((hr  < Hc - sh) ? 1 : 2);
            int rw = (wrr < Wc - ww) ? 0 : ((wrr < Wc - sw) ? 1 : 2);
            rg[m] = rh * 3 + rw;
        }
    }

    // own query
    const int n   = half * 128 + tid;
    const int iy  = n / ww, ix = n % ww;
    const int hr  = wy * wh + iy;
    const int wrr = wx * ww + ix;
    int hs  = hr + sh;   if (hs  >= Hc) hs  -= Hc;
    int wsv = wrr + sw;  if (wsv >= Wc) wsv -= Wc;
    const size_t g     = ((size_t)b * Hc + hs) * Wc + wsv;
    const size_t base4 = g * 45 + (size_t)head * 5;
    const float  scale = 0.223606797749979f;          // 20^-0.5

    float4 q[5];
#pragma unroll
    for (int i = 0; i < 5; i++) {
        float4 t = qp[base4 + i];
        t.x *= scale; t.y *= scale; t.z *= scale; t.w *= scale;
        q[i] = t;
    }
    int myreg = 0;
    if (shifted) {
        int rh = (hr  < Hc - wh) ? 0 : ((hr  < Hc - sh) ? 1 : 2);
        int rw = (wrr < Wc - ww) ? 0 : ((wrr < Wc - sw) ? 1 : 2);
        myreg = rh * 3 + rw;
    }
    __syncthreads();

    float4 acc[5];
#pragma unroll
    for (int i = 0; i < 5; i++) acc[i] = make_float4(0.f, 0.f, 0.f, 0.f);
    float denom = 0.f;

    if (shifted) {
        for (int m = 0; m < 256; m++) {
            float s = 0.f;
#pragma unroll
            for (int i = 0; i < 5; i++) {
                float4 kv = ks[m][i];
                s = fmaf(q[i].x, kv.x, s); s = fmaf(q[i].y, kv.y, s);
                s = fmaf(q[i].z, kv.z, s); s = fmaf(q[i].w, kv.w, s);
            }
            if (rg[m] != myreg) s -= 100.f;
            float p = __expf(s);
            denom += p;
#pragma unroll
            for (int i = 0; i < 5; i++) {
                float4 vv = vsm[m][i];
                acc[i].x = fmaf(p, vv.x, acc[i].x);
                acc[i].y = fmaf(p, vv.y, acc[i].y);
                acc[i].z = fmaf(p, vv.z, acc[i].z);
                acc[i].w = fmaf(p, vv.w, acc[i].w);
            }
        }
    } else {
        for (int m = 0; m < 256; m++) {
            float s = 0.f;
#pragma unroll
            for (int i = 0; i < 5; i++) {
                float4 kv = ks[m][i];
                s = fmaf(q[i].x, kv.x, s); s = fmaf(q[i].y, kv.y, s);
                s = fmaf(q[i].z, kv.z, s); s = fmaf(q[i].w, kv.w, s);
            }
            float p = __expf(s);
            denom += p;
#pragma unroll
            for (int i = 0; i < 5; i++) {
                float4 vv = vsm[m][i];
                acc[i].x = fmaf(p, vv.x, acc[i].x);
                acc[i].y = fmaf(p, vv.y, acc[i].y);
                acc[i].z = fmaf(p, vv.z, acc[i].z);
                acc[i].w = fmaf(p, vv.w, acc[i].w);
            }
        }
    }

    float inv = 1.f / denom;
    float4* op = (float4*)g_attn;
    size_t  ob = g * 15 + (size_t)head * 5;     // 60 floats / token
#pragma unroll
    for (int i = 0; i < 5; i++) {
        float4 t = acc[i];
        t.x *= inv; t.y *= inv; t.z *= inv; t.w *= inv;
        op[ob + i] = t;
    }
}

// ---------------------------------------------------------------------------
// conv3x3 60->12 + PixelShuffle(2) fused.
// ---------------------------------------------------------------------------
__global__ __launch_bounds__(256) void conv_out_k(
    const float* __restrict__ lw, const float* __restrict__ lb,
    float* __restrict__ out)
{
    const int TOT = Bn * 3 * 256 * 256;
    int idx = blockIdx.x * blockDim.x + threadIdx.x;
    if (idx >= TOT) return;
    int w2 = idx & 255;
    int h2 = (idx >> 8) & 255;
    int c  = (idx >> 16) % 3;
    int bb = idx / (3 * 65536);
    int co = c * 4 + (h2 & 1) * 2 + (w2 & 1);
    int h  = h2 >> 1, w = w2 >> 1;
    float acc = lb[co];
#pragma unroll
    for (int kh = 0; kh < 3; kh++) {
        int hh = h + kh - 1;
        if ((unsigned)hh >= (unsigned)Hc) continue;
#pragma unroll
        for (int kw = 0; kw < 3; kw++) {
            int ww2 = w + kw - 1;
            if ((unsigned)ww2 >= (unsigned)Wc) continue;
            const float* fp = g_feat + ((size_t)(bb * Hc + hh) * Wc + ww2) * Cch;
            const float* wp = lw + co * (Cch * 9) + kh * 3 + kw;
#pragma unroll
            for (int ci = 0; ci < Cch; ci++)
                acc = fmaf(fp[ci], wp[ci * 9], acc);
        }
    }
    out[idx] = acc;
}

// ---------------------------------------------------------------------------
// Launch
// ---------------------------------------------------------------------------
extern "C" void kernel_launch(void* const* d_in, const int* in_sizes, int n_in,
                              void* d_out, int out_size)
{
    (void)in_sizes; (void)n_in; (void)out_size;
    const float* x      = (const float*)d_in[0];
    const float* conv_w = (const float*)d_in[1];
    const float* conv_b = (const float*)d_in[2];
    const float* ln1_g  = (const float*)d_in[3];
    const float* ln1_b  = (const float*)d_in[4];
    const float* qkv_w  = (const float*)d_in[5];
    const float* qkv_b  = (const float*)d_in[6];
    const float* proj_w = (const float*)d_in[7];
    const float* proj_b = (const float*)d_in[8];
    const float* ln2_g  = (const float*)d_in[9];
    const float* ln2_b  = (const float*)d_in[10];
    const float* fc1_w  = (const float*)d_in[11];
    const float* fc1_b  = (const float*)d_in[12];
    const float* fc2_w  = (const float*)d_in[13];
    const float* fc2_b  = (const float*)d_in[14];
    const float* last_w = (const float*)d_in[15];
    const float* last_b = (const float*)d_in[16];
    float* out = (float*)d_out;

    // kernel configs:  TM=32 everywhere -> grid 1024
    // qkv : K=60, N=180, NP=192, MG=2 (384 thr), smem 52.1 KB
    // fc1 : K=60, N=120, NP=128, MG=2 (256 thr), smem 37.5 KB
    // proj: K=60, N=60,  NP=64,  MG=4 (256 thr), smem 22.4 KB
    // fc2 : K=120,N=60,  NP=64,  MG=4 (256 thr), smem 44.4 KB
    constexpr int SM_QKV  = (60 * 180 + 180 + 120 + 60 * 32)  * 4;  // 52080
    constexpr int SM_FC1  = (60 * 120 + 120 + 120 + 60 * 32)  * 4;  // 37440
    constexpr int SM_PROJ = (60 * 60  + 60  + 60 * 32)  * 4;        // 22320
    constexpr int SM_FC2  = (120 * 60 + 60  + 120 * 32) * 4;        // 44400

    cudaFuncSetAttribute(ln_gemm_k<60, 180, 192, 2, 32, false, false, 3>,
                         cudaFuncAttributeMaxDynamicSharedMemorySize, SM_QKV);
    cudaFuncSetAttribute(ln_gemm_k<60, 120, 128, 2, 32, true, true, 4>,
                         cudaFuncAttributeMaxDynamicSharedMemorySize, SM_FC1);
    cudaFuncSetAttribute(gemm_resid_k<60, 60, 64, 4, 32, false, 4>,
                         cudaFuncAttributeMaxDynamicSharedMemorySize, SM_PROJ);
    cudaFuncSetAttribute(gemm_resid_k<120, 60, 64, 4, 32, true, 4>,
                         cudaFuncAttributeMaxDynamicSharedMemorySize, SM_FC2);

    conv_in_k<<<(NTOK * Cch + 255) / 256, 256>>>(x, conv_w, conv_b);

    for (int l = 0; l < NL; l++) {
        int i  = l % 6;
        int wi = i % 2;
        int wh = wi ? 8 : 32;
        int ww = wi ? 32 : 8;
        int shifted = (i % 4) >= 2;
        int sh = shifted ? (wi ? 4 : 16) : 0;
        int sw = shifted ? (wi ? 16 : 4) : 0;

        ln_gemm_k<60, 180, 192, 2, 32, false, false, 3>
            <<<NTOK / 32, 384, SM_QKV>>>(ln1_g + l * 60, ln1_b + l * 60,
                                         qkv_w + (size_t)l * 60 * 180,
                                         qkv_b + l * 180);

        attn_k<<<dim3(Bn * 64, NHEADS * 2), 128>>>(wh, ww, sh, sw, shifted);

        gemm_resid_k<60, 60, 64, 4, 32, false, 4>
            <<<NTOK / 32, 256, SM_PROJ>>>(proj_w + (size_t)l * 3600,
                                          proj_b + l * 60);

        ln_gemm_k<60, 120, 128, 2, 32, true, true, 4>
            <<<NTOK / 32, 256, SM_FC1>>>(ln2_g + l * 60, ln2_b + l * 60,
                                         fc1_w + (size_t)l * 7200,
                                         fc1_b + l * 120);

        gemm_resid_k<120, 60, 64, 4, 32, true, 4>
            <<<NTOK / 32, 256, SM_FC2>>>(fc2_w + (size_t)l * 7200,
                                         fc2_b + l * 60);
    }

    conv_out_k<<<(Bn * 3 * 256 * 256 + 255) / 256, 256>>>(last_w, last_b, out);
}

// round 6
// speedup vs baseline: 1.0667x; 1.0039x over previous
#include <cuda_runtime.h>

// ---------------------------------------------------------------------------
// SwinIR-lite forward: conv3x3(3->60) -> 36 x [LN+WindowAttn+res, LN+MLP+res]
// -> conv3x3(60->12) + PixelShuffle(2).  All fp32.  B=2, H=W=128, C=60.
// R4: revert f32x2 (regressed); fix grid-limited occupancy (TM=32 -> grid 1024),
//     8 outputs/thread for issue-ratio + ILP, split attention into half-blocks.
// ---------------------------------------------------------------------------

constexpr int Bn   = 2;
constexpr int Hc   = 128;
constexpr int Wc   = 128;
constexpr int Cch  = 60;
constexpr int NHEADS = 3;
constexpr int NTOK = Bn * Hc * Wc;          // 32768 tokens
constexpr int QKVC = 180;
constexpr int FCC  = 120;
constexpr int NL   = 36;

// Scratch (device globals; no allocation allowed)
__device__ float g_feat[NTOK * Cch];        // 7.5 MB
__device__ float g_qkv [NTOK * QKVC];       // 22.5 MB
__device__ float g_attn[NTOK * Cch];        // 7.5 MB
__device__ float g_mlp [NTOK * FCC];        // 15 MB

// ---------------------------------------------------------------------------
// conv3x3 3->60, NCHW in -> NHWC (token-major) out
// ---------------------------------------------------------------------------
__global__ __launch_bounds__(256) void conv_in_k(
    const float* __restrict__ x, const float* __restrict__ w,
    const float* __restrict__ b)
{
    int idx = blockIdx.x * blockDim.x + threadIdx.x;
    if (idx >= NTOK * Cch) return;
    int co = idx % Cch;
    int p  = idx / Cch;
    int wx = p % Wc;
    int hy = (p / Wc) % Hc;
    int bb = p / (Wc * Hc);
    float acc = b[co];
#pragma unroll
    for (int ci = 0; ci < 3; ci++) {
#pragma unroll
        for (int kh = 0; kh < 3; kh++) {
            int hh = hy + kh - 1;
            if ((unsigned)hh >= (unsigned)Hc) continue;
#pragma unroll
            for (int kw = 0; kw < 3; kw++) {
                int ww2 = wx + kw - 1;
                if ((unsigned)ww2 >= (unsigned)Wc) continue;
                acc += x[((bb * 3 + ci) * Hc + hh) * Wc + ww2] *
                       w[((co * 3 + ci) * 3 + kh) * 3 + kw];
            }
        }
    }
    g_feat[idx] = acc;
}

// ---------------------------------------------------------------------------
// LN (over K=60) + GEMM [T,K]@[K,N] + bias (+ optional Swish).
// Block: NP*MG threads; tile TM tokens; 8 outputs/thread.
// ---------------------------------------------------------------------------
template <int K, int N, int NP, int MG, int TM, bool SWISH, bool OUT_MLP, int MINB>
__global__ __launch_bounds__(NP * MG, MINB) void ln_gemm_k(
    const float* __restrict__ gamma, const float* __restrict__ beta,
    const float* __restrict__ w, const float* __restrict__ bias)
{
    extern __shared__ float sm[];
    float* ws = sm;                  // K*N
    float* bs = sm + K * N;          // N
    float* gs = bs + N;              // K (gamma)
    float* bt = gs + K;              // K (beta)
    float* xs = bt + K;              // K*TM (k-major)
    const int tid = threadIdx.x;
    const int T0  = blockIdx.x * TM;

    for (int i = tid; i < K * N; i += NP * MG) ws[i] = w[i];
    for (int i = tid; i < N; i += NP * MG)     bs[i] = bias[i];
    for (int i = tid; i < K; i += NP * MG)   { gs[i] = gamma[i]; bt[i] = beta[i]; }
    __syncthreads();

    if (tid < TM) {
        const float4* row = (const float4*)(g_feat + (size_t)(T0 + tid) * K);
        float s = 0.f, s2 = 0.f;
#pragma unroll
        for (int i = 0; i < K / 4; i++) {
            float4 v = row[i];
            s  += v.x + v.y + v.z + v.w;
            s2 += v.x * v.x + v.y * v.y + v.z * v.z + v.w * v.w;
            xs[(4 * i + 0) * TM + tid] = v.x;
            xs[(4 * i + 1) * TM + tid] = v.y;
            xs[(4 * i + 2) * TM + tid] = v.z;
            xs[(4 * i + 3) * TM + tid] = v.w;
        }
        float mu  = s * (1.0f / K);
        float var = s2 * (1.0f / K) - mu * mu;
        float rs  = rsqrtf(var + 1e-5f);
#pragma unroll
        for (int k = 0; k < K; k++)
            xs[k * TM + tid] = (xs[k * TM + tid] - mu) * rs * gs[k] + bt[k];
    }
    __syncthreads();

    const int n   = tid % NP;
    const int grp = tid / NP;
    if (n < N) {
        float* out = OUT_MLP ? g_mlp : g_qkv;
        const float bv = bs[n];
        const int mper = TM / MG;
#pragma unroll
        for (int it = 0; it < mper / 8; it++) {
            const int m0 = grp * mper + it * 8;
            float a0 = bv, a1 = bv, a2 = bv, a3 = bv;
            float a4 = bv, a5 = bv, a6 = bv, a7 = bv;
#pragma unroll
            for (int k = 0; k < K; k++) {
                float  wv = ws[k * N + n];
                float4 x0 = *(const float4*)(xs + k * TM + m0);
                float4 x1 = *(const float4*)(xs + k * TM + m0 + 4);
                a0 = fmaf(x0.x, wv, a0);
                a1 = fmaf(x0.y, wv, a1);
                a2 = fmaf(x0.z, wv, a2);
                a3 = fmaf(x0.w, wv, a3);
                a4 = fmaf(x1.x, wv, a4);
                a5 = fmaf(x1.y, wv, a5);
                a6 = fmaf(x1.z, wv, a6);
                a7 = fmaf(x1.w, wv, a7);
            }
            if (SWISH) {
                a0 /= 1.f + __expf(-a0);  a1 /= 1.f + __expf(-a1);
                a2 /= 1.f + __expf(-a2);  a3 /= 1.f + __expf(-a3);
                a4 /= 1.f + __expf(-a4);  a5 /= 1.f + __expf(-a5);
                a6 /= 1.f + __expf(-a6);  a7 /= 1.f + __expf(-a7);
            }
            size_t o = (size_t)(T0 + m0) * N + n;
            out[o]         = a0;  out[o +     N] = a1;
            out[o + 2 * N] = a2;  out[o + 3 * N] = a3;
            out[o + 4 * N] = a4;  out[o + 5 * N] = a5;
            out[o + 6 * N] = a6;  out[o + 7 * N] = a7;
        }
    }
}

// ---------------------------------------------------------------------------
// GEMM [T,K]@[K,N] + bias + residual-add into g_feat.
// ---------------------------------------------------------------------------
template <int K, int N, int NP, int MG, int TM, bool IN_MLP, int MINB>
__global__ __launch_bounds__(NP * MG, MINB) void gemm_resid_k(
    const float* __restrict__ w, const float* __restrict__ bias)
{
    extern __shared__ float sm[];
    float* ws = sm;
    float* bs = sm + K * N;
    float* xs = bs + N;
    const int tid = threadIdx.x;
    const int T0  = blockIdx.x * TM;
    const float* in = IN_MLP ? g_mlp : g_attn;

    for (int i = tid; i < K * N; i += NP * MG) ws[i] = w[i];
    for (int i = tid; i < N; i += NP * MG)     bs[i] = bias[i];

    if (tid < TM) {
        const float4* row = (const float4*)(in + (size_t)(T0 + tid) * K);
#pragma unroll
        for (int i = 0; i < K / 4; i++) {
            float4 v = row[i];
            xs[(4 * i + 0) * TM + tid] = v.x;
            xs[(4 * i + 1) * TM + tid] = v.y;
            xs[(4 * i + 2) * TM + tid] = v.z;
            xs[(4 * i + 3) * TM + tid] = v.w;
        }
    }
    __syncthreads();

    const int n   = tid % NP;
    const int grp = tid / NP;
    if (n < N) {
        const float bv = bs[n];
        const int mper = TM / MG;
#pragma unroll
        for (int it = 0; it < mper / 8; it++) {
            const int m0 = grp * mper + it * 8;
            float a0 = bv, a1 = bv, a2 = bv, a3 = bv;
            float a4 = bv, a5 = bv, a6 = bv, a7 = bv;
#pragma unroll
            for (int k = 0; k < K; k++) {
                float  wv = ws[k * N + n];
                float4 x0 = *(const float4*)(xs + k * TM + m0);
                float4 x1 = *(const float4*)(xs + k * TM + m0 + 4);
                a0 = fmaf(x0.x, wv, a0);
                a1 = fmaf(x0.y, wv, a1);
                a2 = fmaf(x0.z, wv, a2);
                a3 = fmaf(x0.w, wv, a3);
                a4 = fmaf(x1.x, wv, a4);
                a5 = fmaf(x1.y, wv, a5);
                a6 = fmaf(x1.z, wv, a6);
                a7 = fmaf(x1.w, wv, a7);
            }
            size_t o = (size_t)(T0 + m0) * N + n;
            g_feat[o]         += a0;  g_feat[o +     N] += a1;
            g_feat[o + 2 * N] += a2;  g_feat[o + 3 * N] += a3;
            g_feat[o + 4 * N] += a4;  g_feat[o + 5 * N] += a5;
            g_feat[o + 6 * N] += a6;  g_feat[o + 7 * N] += a7;
        }
    }
}

// ---------------------------------------------------------------------------
// Window attention.  Block = (window, head, half); 128 threads = 128 queries,
// full 256-key window K/V in smem.  Roll by index arithmetic; streaming
// softmax without max-subtract (logits tiny; masked = -100).
// ---------------------------------------------------------------------------
__global__ __launch_bounds__(128, 5) void attn_k(int wh, int ww, int sh, int sw,
                                                 int shifted)
{
    __shared__ float4 ks [256][5];
    __shared__ float4 vsm[256][5];
    __shared__ int    rg [256];

    const int tid  = threadIdx.x;
    const int head = blockIdx.y >> 1;
    const int half = blockIdx.y & 1;
    const int win  = blockIdx.x;
    const int nW   = Wc / ww;
    const int perB = (Hc / wh) * nW;
    const int b    = win / perB;
    const int wr_  = win % perB;
    const int wy   = wr_ / nW, wx = wr_ % nW;

    const float4* qp = (const float4*)g_qkv;

    // load 2 K/V rows per thread (keys tid, tid+128)
#pragma unroll
    for (int r = 0; r < 2; r++) {
        int m   = tid + r * 128;
        int iy  = m / ww, ix = m % ww;
        int hr  = wy * wh + iy;
        int wrr = wx * ww + ix;
        int hs  = hr + sh;   if (hs  >= Hc) hs  -= Hc;
        int wsv = wrr + sw;  if (wsv >= Wc) wsv -= Wc;
        size_t gk = ((size_t)b * Hc + hs) * Wc + wsv;
        size_t b4 = gk * 45 + (size_t)head * 5;
#pragma unroll
        for (int i = 0; i < 5; i++) {
            ks [m][i] = qp[b4 + 15 + i];
            vsm[m][i] = qp[b4 + 30 + i];
        }
        if (shifted) {
            int rh = (hr  < Hc - wh) ? 0 : ((hr  < Hc - sh) ? 1 : 2);
            int rw = (wrr < Wc - ww) ? 0 : ((wrr < Wc - sw) ? 1 : 2);
            rg[m] = rh * 3 + rw;
        }
    }

    // own query
    const int n   = half * 128 + tid;
    const int iy  = n / ww, ix = n % ww;
    const int hr  = wy * wh + iy;
    const int wrr = wx * ww + ix;
    int hs  = hr + sh;   if (hs  >= Hc) hs  -= Hc;
    int wsv = wrr + sw;  if (wsv >= Wc) wsv -= Wc;
    const size_t g     = ((size_t)b * Hc + hs) * Wc + wsv;
    const size_t base4 = g * 45 + (size_t)head * 5;
    const float  scale = 0.223606797749979f;          // 20^-0.5

    float4 q[5];
#pragma unroll
    for (int i = 0; i < 5; i++) {
        float4 t = qp[base4 + i];
        t.x *= scale; t.y *= scale; t.z *= scale; t.w *= scale;
        q[i] = t;
    }
    int myreg = 0;
    if (shifted) {
        int rh = (hr  < Hc - wh) ? 0 : ((hr  < Hc - sh) ? 1 : 2);
        int rw = (wrr < Wc - ww) ? 0 : ((wrr < Wc - sw) ? 1 : 2);
        myreg = rh * 3 + rw;
    }
    __syncthreads();

    float4 acc[5];
#pragma unroll
    for (int i = 0; i < 5; i++) acc[i] = make_float4(0.f, 0.f, 0.f, 0.f);
    float denom = 0.f;

    if (shifted) {
        for (int m = 0; m < 256; m++) {
            float s = 0.f;
#pragma unroll
            for (int i = 0; i < 5; i++) {
                float4 kv = ks[m][i];
                s = fmaf(q[i].x, kv.x, s); s = fmaf(q[i].y, kv.y, s);
                s = fmaf(q[i].z, kv.z, s); s = fmaf(q[i].w, kv.w, s);
            }
            if (rg[m] != myreg) s -= 100.f;
            float p = __expf(s);
            denom += p;
#pragma unroll
            for (int i = 0; i < 5; i++) {
                float4 vv = vsm[m][i];
                acc[i].x = fmaf(p, vv.x, acc[i].x);
                acc[i].y = fmaf(p, vv.y, acc[i].y);
                acc[i].z = fmaf(p, vv.z, acc[i].z);
                acc[i].w = fmaf(p, vv.w, acc[i].w);
            }
        }
    } else {
        for (int m = 0; m < 256; m++) {
            float s = 0.f;
#pragma unroll
            for (int i = 0; i < 5; i++) {
                float4 kv = ks[m][i];
                s = fmaf(q[i].x, kv.x, s); s = fmaf(q[i].y, kv.y, s);
                s = fmaf(q[i].z, kv.z, s); s = fmaf(q[i].w, kv.w, s);
            }
            float p = __expf(s);
            denom += p;
#pragma unroll
            for (int i = 0; i < 5; i++) {
                float4 vv = vsm[m][i];
                acc[i].x = fmaf(p, vv.x, acc[i].x);
                acc[i].y = fmaf(p, vv.y, acc[i].y);
                acc[i].z = fmaf(p, vv.z, acc[i].z);
                acc[i].w = fmaf(p, vv.w, acc[i].w);
            }
        }
    }

    float inv = 1.f / denom;
    float4* op = (float4*)g_attn;
    size_t  ob = g * 15 + (size_t)head * 5;     // 60 floats / token
#pragma unroll
    for (int i = 0; i < 5; i++) {
        float4 t = acc[i];
        t.x *= inv; t.y *= inv; t.z *= inv; t.w *= inv;
        op[ob + i] = t;
    }
}

// ---------------------------------------------------------------------------
// conv3x3 60->12 + PixelShuffle(2) fused.
// ---------------------------------------------------------------------------
__global__ __launch_bounds__(256) void conv_out_k(
    const float* __restrict__ lw, const float* __restrict__ lb,
    float* __restrict__ out)
{
    const int TOT = Bn * 3 * 256 * 256;
    int idx = blockIdx.x * blockDim.x + threadIdx.x;
    if (idx >= TOT) return;
    int w2 = idx & 255;
    int h2 = (idx >> 8) & 255;
    int c  = (idx >> 16) % 3;
    int bb = idx / (3 * 65536);
    int co = c * 4 + (h2 & 1) * 2 + (w2 & 1);
    int h  = h2 >> 1, w = w2 >> 1;
    float acc = lb[co];
#pragma unroll
    for (int kh = 0; kh < 3; kh++) {
        int hh = h + kh - 1;
        if ((unsigned)hh >= (unsigned)Hc) continue;
#pragma unroll
        for (int kw = 0; kw < 3; kw++) {
            int ww2 = w + kw - 1;
            if ((unsigned)ww2 >= (unsigned)Wc) continue;
            const float* fp = g_feat + ((size_t)(bb * Hc + hh) * Wc + ww2) * Cch;
            const float* wp = lw + co * (Cch * 9) + kh * 3 + kw;
#pragma unroll
            for (int ci = 0; ci < Cch; ci++)
                acc = fmaf(fp[ci], wp[ci * 9], acc);
        }
    }
    out[idx] = acc;
}

// ---------------------------------------------------------------------------
// Launch
// ---------------------------------------------------------------------------
extern "C" void kernel_launch(void* const* d_in, const int* in_sizes, int n_in,
                              void* d_out, int out_size)
{
    (void)in_sizes; (void)n_in; (void)out_size;
    const float* x      = (const float*)d_in[0];
    const float* conv_w = (const float*)d_in[1];
    const float* conv_b = (const float*)d_in[2];
    const float* ln1_g  = (const float*)d_in[3];
    const float* ln1_b  = (const float*)d_in[4];
    const float* qkv_w  = (const float*)d_in[5];
    const float* qkv_b  = (const float*)d_in[6];
    const float* proj_w = (const float*)d_in[7];
    const float* proj_b = (const float*)d_in[8];
    const float* ln2_g  = (const float*)d_in[9];
    const float* ln2_b  = (const float*)d_in[10];
    const float* fc1_w  = (const float*)d_in[11];
    const float* fc1_b  = (const float*)d_in[12];
    const float* fc2_w  = (const float*)d_in[13];
    const float* fc2_b  = (const float*)d_in[14];
    const float* last_w = (const float*)d_in[15];
    const float* last_b = (const float*)d_in[16];
    float* out = (float*)d_out;

    // kernel configs:  TM=32 everywhere -> grid 1024
    // qkv : K=60, N=180, NP=192, MG=2 (384 thr), smem 52.1 KB
    // fc1 : K=60, N=120, NP=128, MG=2 (256 thr), smem 37.5 KB
    // proj: K=60, N=60,  NP=64,  MG=4 (256 thr), smem 22.4 KB
    // fc2 : K=120,N=60,  NP=64,  MG=4 (256 thr), smem 44.4 KB
    constexpr int SM_QKV  = (60 * 180 + 180 + 120 + 60 * 32)  * 4;  // 52080
    constexpr int SM_FC1  = (60 * 120 + 120 + 120 + 60 * 32)  * 4;  // 37440
    constexpr int SM_PROJ = (60 * 60  + 60  + 60 * 32)  * 4;        // 22320
    constexpr int SM_FC2  = (120 * 60 + 60  + 120 * 32) * 4;        // 44400

    cudaFuncSetAttribute(ln_gemm_k<60, 180, 192, 2, 32, false, false, 3>,
                         cudaFuncAttributeMaxDynamicSharedMemorySize, SM_QKV);
    cudaFuncSetAttribute(ln_gemm_k<60, 120, 128, 2, 32, true, true, 4>,
                         cudaFuncAttributeMaxDynamicSharedMemorySize, SM_FC1);
    cudaFuncSetAttribute(gemm_resid_k<60, 60, 64, 4, 32, false, 4>,
                         cudaFuncAttributeMaxDynamicSharedMemorySize, SM_PROJ);
    cudaFuncSetAttribute(gemm_resid_k<120, 60, 64, 4, 32, true, 4>,
                         cudaFuncAttributeMaxDynamicSharedMemorySize, SM_FC2);

    conv_in_k<<<(NTOK * Cch + 255) / 256, 256>>>(x, conv_w, conv_b);

    for (int l = 0; l < NL; l++) {
        int i  = l % 6;
        int wi = i % 2;
        int wh = wi ? 8 : 32;
        int ww = wi ? 32 : 8;
        int shifted = (i % 4) >= 2;
        int sh = shifted ? (wi ? 4 : 16) : 0;
        int sw = shifted ? (wi ? 16 : 4) : 0;

        ln_gemm_k<60, 180, 192, 2, 32, false, false, 3>
            <<<NTOK / 32, 384, SM_QKV>>>(ln1_g + l * 60, ln1_b + l * 60,
                                         qkv_w + (size_t)l * 60 * 180,
                                         qkv_b + l * 180);

        attn_k<<<dim3(Bn * 64, NHEADS * 2), 128>>>(wh, ww, sh, sw, shifted);

        gemm_resid_k<60, 60, 64, 4, 32, false, 4>
            <<<NTOK / 32, 256, SM_PROJ>>>(proj_w + (size_t)l * 3600,
                                          proj_b + l * 60);

        ln_gemm_k<60, 120, 128, 2, 32, true, true, 4>
            <<<NTOK / 32, 256, SM_FC1>>>(ln2_g + l * 60, ln2_b + l * 60,
                                         fc1_w + (size_t)l * 7200,
                                         fc1_b + l * 120);

        gemm_resid_k<120, 60, 64, 4, 32, true, 4>
            <<<NTOK / 32, 256, SM_FC2>>>(fc2_w + (size_t)l * 7200,
                                         fc2_b + l * 60);
    }

    conv_out_k<<<(Bn * 3 * 256 * 256 + 255) / 256, 256>>>(last_w, last_b, out);
}

// round 8
// speedup vs baseline: 1.3917x; 1.3047x over previous
#include <cuda_runtime.h>

// ---------------------------------------------------------------------------
// SwinIR-lite forward: conv3x3(3->60) -> 36 x [LN+WindowAttn+res, LN+MLP+res]
// -> conv3x3(60->12) + PixelShuffle(2).  All fp32.  B=2, H=W=128, C=60.
// R6 (resubmit; R7 bench was an infra failure): GEMMs use 4Mx4N register tiles
// (1 LDS.128 x + 1 LDS.128 w per 16 FFMA, float4 stores); TM=32 grid=1024;
// attention in R2 form (one block per (window, head), 256 query threads).
// ---------------------------------------------------------------------------

constexpr int Bn   = 2;
constexpr int Hc   = 128;
constexpr int Wc   = 128;
constexpr int Cch  = 60;
constexpr int NHEADS = 3;
constexpr int NTOK = Bn * Hc * Wc;          // 32768 tokens
constexpr int QKVC = 180;
constexpr int FCC  = 120;
constexpr int NL   = 36;

// Scratch (device globals; no allocation allowed)
__device__ float g_feat[NTOK * Cch];        // 7.5 MB
__device__ float g_qkv [NTOK * QKVC];       // 22.5 MB
__device__ float g_attn[NTOK * Cch];        // 7.5 MB
__device__ float g_mlp [NTOK * FCC];        // 15 MB

// ---------------------------------------------------------------------------
// conv3x3 3->60, NCHW in -> NHWC (token-major) out
// ---------------------------------------------------------------------------
__global__ __launch_bounds__(256) void conv_in_k(
    const float* __restrict__ x, const float* __restrict__ w,
    const float* __restrict__ b)
{
    int idx = blockIdx.x * blockDim.x + threadIdx.x;
    if (idx >= NTOK * Cch) return;
    int co = idx % Cch;
    int p  = idx / Cch;
    int wx = p % Wc;
    int hy = (p / Wc) % Hc;
    int bb = p / (Wc * Hc);
    float acc = b[co];
#pragma unroll
    for (int ci = 0; ci < 3; ci++) {
#pragma unroll
        for (int kh = 0; kh < 3; kh++) {
            int hh = hy + kh - 1;
            if ((unsigned)hh >= (unsigned)Hc) continue;
#pragma unroll
            for (int kw = 0; kw < 3; kw++) {
                int ww2 = wx + kw - 1;
                if ((unsigned)ww2 >= (unsigned)Wc) continue;
                acc += x[((bb * 3 + ci) * Hc + hh) * Wc + ww2] *
                       w[((co * 3 + ci) * 3 + kh) * 3 + kw];
            }
        }
    }
    g_feat[idx] = acc;
}

// ---------------------------------------------------------------------------
// GEMM core: each thread computes a 4M x 4N register tile.
//   per k: 1 LDS.128 (x, 4 rows) + 1 LDS.128 (w, 4 cols) -> 16 FFMA.
// Thread map: t = ng*MG + mg;  n0 = ng*4, m0 = mg*4.  Used = (N/4)*MG threads.
// ---------------------------------------------------------------------------

// LN (over K) + GEMM [T,K]@[K,N] + bias (+ optional Swish) -> out.
template <int K, int N, int MG, int TM, bool SWISH, bool OUT_MLP, int NTHR, int MINB>
__global__ __launch_bounds__(NTHR, MINB) void ln_gemm_k(
    const float* __restrict__ gamma, const float* __restrict__ beta,
    const float* __restrict__ w, const float* __restrict__ bias)
{
    extern __shared__ float sm[];
    float* ws = sm;                  // K*N
    float* bs = sm + K * N;          // N
    float* gs = bs + N;              // K (gamma)
    float* bt = gs + K;              // K (beta)
    float* xs = bt + K;              // K*TM (k-major)
    const int tid = threadIdx.x;
    const int T0  = blockIdx.x * TM;

    {   // cooperative weight load (float4)
        const float4* wg = (const float4*)w;
        float4*       w4 = (float4*)ws;
        for (int i = tid; i < K * N / 4; i += NTHR) w4[i] = wg[i];
    }
    for (int i = tid; i < N; i += NTHR)  bs[i] = bias[i];
    for (int i = tid; i < K; i += NTHR) { gs[i] = gamma[i]; bt[i] = beta[i]; }
    __syncthreads();

    if (tid < TM) {
        const float4* row = (const float4*)(g_feat + (size_t)(T0 + tid) * K);
        float s = 0.f, s2 = 0.f;
#pragma unroll
        for (int i = 0; i < K / 4; i++) {
            float4 v = row[i];
            s  += v.x + v.y + v.z + v.w;
            s2 += v.x * v.x + v.y * v.y + v.z * v.z + v.w * v.w;
            xs[(4 * i + 0) * TM + tid] = v.x;
            xs[(4 * i + 1) * TM + tid] = v.y;
            xs[(4 * i + 2) * TM + tid] = v.z;
            xs[(4 * i + 3) * TM + tid] = v.w;
        }
        float mu  = s * (1.0f / K);
        float var = s2 * (1.0f / K) - mu * mu;
        float rs  = rsqrtf(var + 1e-5f);
#pragma unroll
        for (int k = 0; k < K; k++)
            xs[k * TM + tid] = (xs[k * TM + tid] - mu) * rs * gs[k] + bt[k];
    }
    __syncthreads();

    constexpr int USED = (N / 4) * MG;
    if (tid < USED) {
        const int ng = tid / MG, mg = tid % MG;
        const int n0 = ng * 4,   m0 = mg * 4;
        float4 bv = *(const float4*)(bs + n0);
        float4 a0 = bv, a1 = bv, a2 = bv, a3 = bv;   // rows m0..m0+3
#pragma unroll
        for (int k = 0; k < K; k++) {
            float4 xv = *(const float4*)(xs + k * TM + m0);
            float4 wv = *(const float4*)(ws + k * N + n0);
            a0.x = fmaf(xv.x, wv.x, a0.x); a0.y = fmaf(xv.x, wv.y, a0.y);
            a0.z = fmaf(xv.x, wv.z, a0.z); a0.w = fmaf(xv.x, wv.w, a0.w);
            a1.x = fmaf(xv.y, wv.x, a1.x); a1.y = fmaf(xv.y, wv.y, a1.y);
            a1.z = fmaf(xv.y, wv.z, a1.z); a1.w = fmaf(xv.y, wv.w, a1.w);
            a2.x = fmaf(xv.z, wv.x, a2.x); a2.y = fmaf(xv.z, wv.y, a2.y);
            a2.z = fmaf(xv.z, wv.z, a2.z); a2.w = fmaf(xv.z, wv.w, a2.w);
            a3.x = fmaf(xv.w, wv.x, a3.x); a3.y = fmaf(xv.w, wv.y, a3.y);
            a3.z = fmaf(xv.w, wv.z, a3.z); a3.w = fmaf(xv.w, wv.w, a3.w);
        }
        if (SWISH) {
            a0.x /= 1.f + __expf(-a0.x); a0.y /= 1.f + __expf(-a0.y);
            a0.z /= 1.f + __expf(-a0.z); a0.w /= 1.f + __expf(-a0.w);
            a1.x /= 1.f + __expf(-a1.x); a1.y /= 1.f + __expf(-a1.y);
            a1.z /= 1.f + __expf(-a1.z); a1.w /= 1.f + __expf(-a1.w);
            a2.x /= 1.f + __expf(-a2.x); a2.y /= 1.f + __expf(-a2.y);
            a2.z /= 1.f + __expf(-a2.z); a2.w /= 1.f + __expf(-a2.w);
            a3.x /= 1.f + __expf(-a3.x); a3.y /= 1.f + __expf(-a3.y);
            a3.z /= 1.f + __expf(-a3.z); a3.w /= 1.f + __expf(-a3.w);
        }
        float* out = OUT_MLP ? g_mlp : g_qkv;
        size_t ob = (size_t)(T0 + m0) * N + n0;
        *(float4*)(out + ob)         = a0;
        *(float4*)(out + ob + N)     = a1;
        *(float4*)(out + ob + 2 * N) = a2;
        *(float4*)(out + ob + 3 * N) = a3;
    }
}

// GEMM [T,K]@[K,N] + bias + residual-add into g_feat.
template <int K, int N, int MG, int TM, bool IN_MLP, int NTHR, int MINB>
__global__ __launch_bounds__(NTHR, MINB) void gemm_resid_k(
    const float* __restrict__ w, const float* __restrict__ bias)
{
    extern __shared__ float sm[];
    float* ws = sm;
    float* bs = sm + K * N;
    float* xs = bs + N;
    const int tid = threadIdx.x;
    const int T0  = blockIdx.x * TM;
    const float* in = IN_MLP ? g_mlp : g_attn;

    {
        const float4* wg = (const float4*)w;
        float4*       w4 = (float4*)ws;
        for (int i = tid; i < K * N / 4; i += NTHR) w4[i] = wg[i];
    }
    for (int i = tid; i < N; i += NTHR) bs[i] = bias[i];

    if (tid < TM) {
        const float4* row = (const float4*)(in + (size_t)(T0 + tid) * K);
#pragma unroll
        for (int i = 0; i < K / 4; i++) {
            float4 v = row[i];
            xs[(4 * i + 0) * TM + tid] = v.x;
            xs[(4 * i + 1) * TM + tid] = v.y;
            xs[(4 * i + 2) * TM + tid] = v.z;
            xs[(4 * i + 3) * TM + tid] = v.w;
        }
    }
    __syncthreads();

    constexpr int USED = (N / 4) * MG;
    if (tid < USED) {
        const int ng = tid / MG, mg = tid % MG;
        const int n0 = ng * 4,   m0 = mg * 4;
        float4 bv = *(const float4*)(bs + n0);
        float4 a0 = bv, a1 = bv, a2 = bv, a3 = bv;
#pragma unroll
        for (int k = 0; k < K; k++) {
            float4 xv = *(const float4*)(xs + k * TM + m0);
            float4 wv = *(const float4*)(ws + k * N + n0);
            a0.x = fmaf(xv.x, wv.x, a0.x); a0.y = fmaf(xv.x, wv.y, a0.y);
            a0.z = fmaf(xv.x, wv.z, a0.z); a0.w = fmaf(xv.x, wv.w, a0.w);
            a1.x = fmaf(xv.y, wv.x, a1.x); a1.y = fmaf(xv.y, wv.y, a1.y);
            a1.z = fmaf(xv.y, wv.z, a1.z); a1.w = fmaf(xv.y, wv.w, a1.w);
            a2.x = fmaf(xv.z, wv.x, a2.x); a2.y = fmaf(xv.z, wv.y, a2.y);
            a2.z = fmaf(xv.z, wv.z, a2.z); a2.w = fmaf(xv.z, wv.w, a2.w);
            a3.x = fmaf(xv.w, wv.x, a3.x); a3.y = fmaf(xv.w, wv.y, a3.y);
            a3.z = fmaf(xv.w, wv.z, a3.z); a3.w = fmaf(xv.w, wv.w, a3.w);
        }
        size_t ob = (size_t)(T0 + m0) * N + n0;
        float4 r0 = *(const float4*)(g_feat + ob);
        float4 r1 = *(const float4*)(g_feat + ob + N);
        float4 r2 = *(const float4*)(g_feat + ob + 2 * N);
        float4 r3 = *(const float4*)(g_feat + ob + 3 * N);
        r0.x += a0.x; r0.y += a0.y; r0.z += a0.z; r0.w += a0.w;
        r1.x += a1.x; r1.y += a1.y; r1.z += a1.z; r1.w += a1.w;
        r2.x += a2.x; r2.y += a2.y; r2.z += a2.z; r2.w += a2.w;
        r3.x += a3.x; r3.y += a3.y; r3.z += a3.z; r3.w += a3.w;
        *(float4*)(g_feat + ob)         = r0;
        *(float4*)(g_feat + ob + N)     = r1;
        *(float4*)(g_feat + ob + 2 * N) = r2;
        *(float4*)(g_feat + ob + 3 * N) = r3;
    }
}

// ---------------------------------------------------------------------------
// Window attention (R2 form).  Block = (window, head), 256 threads = queries.
// Roll by index arithmetic; streaming softmax w/o max-subtract (logits tiny;
// masked = -100).
// ---------------------------------------------------------------------------
__global__ __launch_bounds__(256) void attn_k(int wh, int ww, int sh, int sw,
                                              int shifted)
{
    __shared__ float4 ks [256][5];
    __shared__ float4 vsm[256][5];
    __shared__ int    rg [256];

    const int n    = threadIdx.x;
    const int head = blockIdx.y;
    const int win  = blockIdx.x;
    const int nW   = Wc / ww;
    const int perB = (Hc / wh) * nW;
    const int b    = win / perB;
    const int wr_  = win % perB;
    const int wy   = wr_ / nW, wx = wr_ % nW;
    const int iy   = n / ww,   ix = n % ww;
    const int hr   = wy * wh + iy;
    const int wrr  = wx * ww + ix;
    int hs = hr + sh;   if (hs  >= Hc) hs  -= Hc;
    int wsv = wrr + sw; if (wsv >= Wc) wsv -= Wc;
    const size_t g = ((size_t)b * Hc + hs) * Wc + wsv;

    const float4* qp    = (const float4*)g_qkv;
    const size_t  base4 = g * 45 + (size_t)head * 5;   // 180 floats / token
    const float   scale = 0.223606797749979f;          // 20^-0.5

    float4 q[5];
#pragma unroll
    for (int i = 0; i < 5; i++) {
        float4 t = qp[base4 + i];
        t.x *= scale; t.y *= scale; t.z *= scale; t.w *= scale;
        q[i] = t;
        ks [n][i] = qp[base4 + 15 + i];
        vsm[n][i] = qp[base4 + 30 + i];
    }
    int myreg = 0;
    if (shifted) {
        int rh = (hr  < Hc - wh) ? 0 : ((hr  < Hc - sh) ? 1 : 2);
        int rw = (wrr < Wc - ww) ? 0 : ((wrr < Wc - sw) ? 1 : 2);
        myreg = rh * 3 + rw;
        rg[n] = myreg;
    }
    __syncthreads();

    float4 acc[5];
#pragma unroll
    for (int i = 0; i < 5; i++) acc[i] = make_float4(0.f, 0.f, 0.f, 0.f);
    float denom = 0.f;

    if (shifted) {
        for (int m = 0; m < 256; m++) {
            float s = 0.f;
#pragma unroll
            for (int i = 0; i < 5; i++) {
                float4 kv = ks[m][i];
                s = fmaf(q[i].x, kv.x, s); s = fmaf(q[i].y, kv.y, s);
                s = fmaf(q[i].z, kv.z, s); s = fmaf(q[i].w, kv.w, s);
            }
            if (rg[m] != myreg) s -= 100.f;
            float p = __expf(s);
            denom += p;
#pragma unroll
            for (int i = 0; i < 5; i++) {
                float4 vv = vsm[m][i];
                acc[i].x = fmaf(p, vv.x, acc[i].x);
                acc[i].y = fmaf(p, vv.y, acc[i].y);
                acc[i].z = fmaf(p, vv.z, acc[i].z);
                acc[i].w = fmaf(p, vv.w, acc[i].w);
            }
        }
    } else {
        for (int m = 0; m < 256; m++) {
            float s = 0.f;
#pragma unroll
            for (int i = 0; i < 5; i++) {
                float4 kv = ks[m][i];
                s = fmaf(q[i].x, kv.x, s); s = fmaf(q[i].y, kv.y, s);
                s = fmaf(q[i].z, kv.z, s); s = fmaf(q[i].w, kv.w, s);
            }
            float p = __expf(s);
            denom += p;
#pragma unroll
            for (int i = 0; i < 5; i++) {
                float4 vv = vsm[m][i];
                acc[i].x = fmaf(p, vv.x, acc[i].x);
                acc[i].y = fmaf(p, vv.y, acc[i].y);
                acc[i].z = fmaf(p, vv.z, acc[i].z);
                acc[i].w = fmaf(p, vv.w, acc[i].w);
            }
        }
    }

    float inv = 1.f / denom;
    float4* op = (float4*)g_attn;
    size_t  ob = g * 15 + (size_t)head * 5;     // 60 floats / token
#pragma unroll
    for (int i = 0; i < 5; i++) {
        float4 t = acc[i];
        t.x *= inv; t.y *= inv; t.z *= inv; t.w *= inv;
        op[ob + i] = t;
    }
}

// ---------------------------------------------------------------------------
// conv3x3 60->12 + PixelShuffle(2) fused.
// ---------------------------------------------------------------------------
__global__ __launch_bounds__(256) void conv_out_k(
    const float* __restrict__ lw, const float* __restrict__ lb,
    float* __restrict__ out)
{
    const int TOT = Bn * 3 * 256 * 256;
    int idx = blockIdx.x * blockDim.x + threadIdx.x;
    if (idx >= TOT) return;
    int w2 = idx & 255;
    int h2 = (idx >> 8) & 255;
    int c  = (idx >> 16) % 3;
    int bb = idx / (3 * 65536);
    int co = c * 4 + (h2 & 1) * 2 + (w2 & 1);
    int h  = h2 >> 1, w = w2 >> 1;
    float acc = lb[co];
#pragma unroll
    for (int kh = 0; kh < 3; kh++) {
        int hh = h + kh - 1;
        if ((unsigned)hh >= (unsigned)Hc) continue;
#pragma unroll
        for (int kw = 0; kw < 3; kw++) {
            int ww2 = w + kw - 1;
            if ((unsigned)ww2 >= (unsigned)Wc) continue;
            const float* fp = g_feat + ((size_t)(bb * Hc + hh) * Wc + ww2) * Cch;
            const float* wp = lw + co * (Cch * 9) + kh * 3 + kw;
#pragma unroll
            for (int ci = 0; ci < Cch; ci++)
                acc = fmaf(fp[ci], wp[ci * 9], acc);
        }
    }
    out[idx] = acc;
}

// ---------------------------------------------------------------------------
// Launch
// ---------------------------------------------------------------------------
extern "C" void kernel_launch(void* const* d_in, const int* in_sizes, int n_in,
                              void* d_out, int out_size)
{
    (void)in_sizes; (void)n_in; (void)out_size;
    const float* x      = (const float*)d_in[0];
    const float* conv_w = (const float*)d_in[1];
    const float* conv_b = (const float*)d_in[2];
    const float* ln1_g  = (const float*)d_in[3];
    const float* ln1_b  = (const float*)d_in[4];
    const float* qkv_w  = (const float*)d_in[5];
    const float* qkv_b  = (const float*)d_in[6];
    const float* proj_w = (const float*)d_in[7];
    const float* proj_b = (const float*)d_in[8];
    const float* ln2_g  = (const float*)d_in[9];
    const float* ln2_b  = (const float*)d_in[10];
    const float* fc1_w  = (const float*)d_in[11];
    const float* fc1_b  = (const float*)d_in[12];
    const float* fc2_w  = (const float*)d_in[13];
    const float* fc2_b  = (const float*)d_in[14];
    const float* last_w = (const float*)d_in[15];
    const float* last_b = (const float*)d_in[16];
    float* out = (float*)d_out;

    // All GEMMs: TM=32, MG=8 (4Mx4N tiles), grid 1024.
    // qkv : N=180 -> 45 ngroups * 8 = 360 used, 384 thr, smem 52080
    // fc1 : N=120 -> 30 * 8 = 240 used, 256 thr, smem 37440
    // proj: N=60  -> 15 * 8 = 120 used, 128 thr, smem 22320
    // fc2 : N=60, K=120 -> 120 used, 128 thr, smem 44400
    constexpr int SM_QKV  = (60 * 180 + 180 + 120 + 60 * 32)  * 4;  // 52080
    constexpr int SM_FC1  = (60 * 120 + 120 + 120 + 60 * 32)  * 4;  // 37440
    constexpr int SM_PROJ = (60 * 60  + 60  + 60 * 32)  * 4;        // 22320
    constexpr int SM_FC2  = (120 * 60 + 60  + 120 * 32) * 4;        // 44400

    cudaFuncSetAttribute(ln_gemm_k<60, 180, 8, 32, false, false, 384, 3>,
                         cudaFuncAttributeMaxDynamicSharedMemorySize, SM_QKV);
    cudaFuncSetAttribute(ln_gemm_k<60, 120, 8, 32, true, true, 256, 4>,
                         cudaFuncAttributeMaxDynamicSharedMemorySize, SM_FC1);
    cudaFuncSetAttribute(gemm_resid_k<60, 60, 8, 32, false, 128, 8>,
                         cudaFuncAttributeMaxDynamicSharedMemorySize, SM_PROJ);
    cudaFuncSetAttribute(gemm_resid_k<120, 60, 8, 32, true, 128, 5>,
                         cudaFuncAttributeMaxDynamicSharedMemorySize, SM_FC2);

    conv_in_k<<<(NTOK * Cch + 255) / 256, 256>>>(x, conv_w, conv_b);

    for (int l = 0; l < NL; l++) {
        int i  = l % 6;
        int wi = i % 2;
        int wh = wi ? 8 : 32;
        int ww = wi ? 32 : 8;
        int shifted = (i % 4) >= 2;
        int sh = shifted ? (wi ? 4 : 16) : 0;
        int sw = shifted ? (wi ? 16 : 4) : 0;

        ln_gemm_k<60, 180, 8, 32, false, false, 384, 3>
            <<<NTOK / 32, 384, SM_QKV>>>(ln1_g + l * 60, ln1_b + l * 60,
                                         qkv_w + (size_t)l * 60 * 180,
                                         qkv_b + l * 180);

        attn_k<<<dim3(Bn * 64, NHEADS), 256>>>(wh, ww, sh, sw, shifted);

        gemm_resid_k<60, 60, 8, 32, false, 128, 8>
            <<<NTOK / 32, 128, SM_PROJ>>>(proj_w + (size_t)l * 3600,
                                          proj_b + l * 60);

        ln_gemm_k<60, 120, 8, 32, true, true, 256, 4>
            <<<NTOK / 32, 256, SM_FC1>>>(ln2_g + l * 60, ln2_b + l * 60,
                                         fc1_w + (size_t)l * 7200,
                                         fc1_b + l * 120);

        gemm_resid_k<120, 60, 8, 32, true, 128, 5>
            <<<NTOK / 32, 128, SM_FC2>>>(fc2_w + (size_t)l * 7200,
                                         fc2_b + l * 60);
    }

    conv_out_k<<<(Bn * 3 * 256 * 256 + 255) / 256, 256>>>(last_w, last_b, out);
}